// round 15
// baseline (speedup 1.0000x reference)
#include <cuda_runtime.h>
#include <cuda_fp16.h>
#include <cstdint>

// ============================================================================
// BitLinear: out[16384, 2048] = X[16384, 2048] @ T^T * scale + bias
// T = ternary(W) exact in fp16, X in fp16, fp32 accumulate via mma.sync (HMMA).
// R15 (FINAL): byte-identical resubmission of R13, the measured optimum
// (332.3us): fused single-launch prep (W ternarize single-pass + X convert,
// __ldcs inputs) + frozen R5 GEMM mainloop (2 CTAs/SM, 256 thr, warp 64x32,
// BK=64, 3-stage cp.async) + __stcs epilogue.
// ============================================================================

#define M_TOTAL 16384
#define N_TOTAL 2048
#define K_TOTAL 2048

#define BM 128
#define BN 128
#define BK 64
#define STAGES 3
#define KITERS (K_TOTAL / BK)          // 32

#define A_TILE_BYTES (BM * BK * 2)     // 16384
#define B_TILE_BYTES (BN * BK * 2)     // 16384
#define STAGE_BYTES  (A_TILE_BYTES + B_TILE_BYTES)   // 32768
#define SMEM_BYTES   (STAGES * STAGE_BYTES)          // 98304

// Scratch (device globals: allocation-free per harness rules)
__device__ __half g_Xh[(size_t)M_TOTAL * K_TOTAL];   // 64 MB
__device__ __half g_Wq[(size_t)N_TOTAL * K_TOTAL];   // 8 MB
__device__ float  g_scale[N_TOTAL];

// ---------------------------------------------------------------------------
// helpers
// ---------------------------------------------------------------------------
__device__ __forceinline__ uint32_t smem_u32(const void* p) {
    uint32_t a;
    asm("{ .reg .u64 t; cvta.to.shared.u64 t, %1; cvt.u32.u64 %0, t; }" : "=r"(a) : "l"(p));
    return a;
}
__device__ __forceinline__ void cp_async16(uint32_t s, const void* g) {
    asm volatile("cp.async.cg.shared.global [%0], [%1], 16;" :: "r"(s), "l"(g));
}
__device__ __forceinline__ void cp_commit() { asm volatile("cp.async.commit_group;"); }
template <int N> __device__ __forceinline__ void cp_wait() {
    asm volatile("cp.async.wait_group %0;" :: "n"(N));
}
__device__ __forceinline__ uint32_t swz(uint32_t off) { return off ^ ((off >> 3) & 0x70); }

__device__ __forceinline__ void ldsm_x4(uint32_t& r0, uint32_t& r1, uint32_t& r2,
                                        uint32_t& r3, uint32_t addr) {
    asm volatile("ldmatrix.sync.aligned.m8n8.x4.shared.b16 {%0,%1,%2,%3}, [%4];"
                 : "=r"(r0), "=r"(r1), "=r"(r2), "=r"(r3) : "r"(addr));
}
__device__ __forceinline__ void mma16816(float& c0, float& c1, float& c2, float& c3,
                                         uint32_t a0, uint32_t a1, uint32_t a2, uint32_t a3,
                                         uint32_t b0, uint32_t b1) {
    asm volatile(
        "mma.sync.aligned.m16n8k16.row.col.f32.f16.f16.f32 "
        "{%0,%1,%2,%3}, {%4,%5,%6,%7}, {%8,%9}, {%0,%1,%2,%3};"
        : "+f"(c0), "+f"(c1), "+f"(c2), "+f"(c3)
        : "r"(a0), "r"(a1), "r"(a2), "r"(a3), "r"(b0), "r"(b1));
}

// ---------------------------------------------------------------------------
// Fused prep: blocks [0, 2048) ternarize W (single pass, row cached in regs);
//             rest convert X (16 floats/thread, MLP=4). __ldcs inputs.
// ---------------------------------------------------------------------------
#define NBLK_W N_TOTAL
#define NBLK_X ((M_TOTAL * K_TOTAL) / (256 * 16))   // 8192

__global__ void prep_kernel(const float* __restrict__ w, const float4* __restrict__ x) {
    if (blockIdx.x < NBLK_W) {
        __shared__ float red[8];
        int row = blockIdx.x;
        const float4* wr = (const float4*)(w + (size_t)row * K_TOTAL);
        // cache 8 floats/thread (2 float4), single DRAM pass, evict-first
        float4 v0 = __ldcs(&wr[threadIdx.x]);
        float4 v1 = __ldcs(&wr[threadIdx.x + 256]);
        float m = fmaxf(fmaxf(fmaxf(fabsf(v0.x), fabsf(v0.y)), fmaxf(fabsf(v0.z), fabsf(v0.w))),
                        fmaxf(fmaxf(fabsf(v1.x), fabsf(v1.y)), fmaxf(fabsf(v1.z), fabsf(v1.w))));
        #pragma unroll
        for (int o = 16; o; o >>= 1) m = fmaxf(m, __shfl_xor_sync(0xffffffffu, m, o));
        if ((threadIdx.x & 31) == 0) red[threadIdx.x >> 5] = m;
        __syncthreads();
        if (threadIdx.x < 8) {
            float v = red[threadIdx.x];
            #pragma unroll
            for (int o = 4; o; o >>= 1) v = fmaxf(v, __shfl_xor_sync(0xffu, v, o));
            if (threadIdx.x == 0) red[0] = v;
        }
        __syncthreads();
        float s = fmaxf(red[0], 1e-6f);
        if (threadIdx.x == 0) g_scale[row] = s;

        float q[8] = {v0.x, v0.y, v0.z, v0.w, v1.x, v1.y, v1.z, v1.w};
        __half h[8];
        #pragma unroll
        for (int i = 0; i < 8; i++) {
            float v = __fdiv_rn(q[i], s);   // IEEE div: match reference at +/-0.5 boundary
            h[i] = __float2half_rn((v > 0.5f) ? 1.f : ((v < -0.5f) ? -1.f : 0.f));
        }
        __half* dst = g_Wq + (size_t)row * K_TOTAL;
        uint2 p0 = make_uint2(*(uint32_t*)&h[0], *(uint32_t*)&h[2]);  // h[0..3]
        uint2 p1 = make_uint2(*(uint32_t*)&h[4], *(uint32_t*)&h[6]);  // h[4..7]
        *(uint2*)(dst + 4 * (size_t)threadIdx.x)         = p0;
        *(uint2*)(dst + 4 * ((size_t)threadIdx.x + 256)) = p1;
    } else {
        // X convert: 16 floats per thread, 4 independent float4 loads (MLP=4),
        // evict-first reads (X fp32 is never read again)
        size_t u = (size_t)(blockIdx.x - NBLK_W) * 256 + threadIdx.x;  // 16-float unit
        float4 v0 = __ldcs(&x[4 * u + 0]);
        float4 v1 = __ldcs(&x[4 * u + 1]);
        float4 v2 = __ldcs(&x[4 * u + 2]);
        float4 v3 = __ldcs(&x[4 * u + 3]);
        uint4 o0, o1;
        __half2 h;
        h = __floats2half2_rn(v0.x, v0.y); o0.x = *(uint32_t*)&h;
        h = __floats2half2_rn(v0.z, v0.w); o0.y = *(uint32_t*)&h;
        h = __floats2half2_rn(v1.x, v1.y); o0.z = *(uint32_t*)&h;
        h = __floats2half2_rn(v1.z, v1.w); o0.w = *(uint32_t*)&h;
        h = __floats2half2_rn(v2.x, v2.y); o1.x = *(uint32_t*)&h;
        h = __floats2half2_rn(v2.z, v2.w); o1.y = *(uint32_t*)&h;
        h = __floats2half2_rn(v3.x, v3.y); o1.z = *(uint32_t*)&h;
        h = __floats2half2_rn(v3.z, v3.w); o1.w = *(uint32_t*)&h;
        ((uint4*)g_Xh)[2 * u + 0] = o0;
        ((uint4*)g_Xh)[2 * u + 1] = o1;
    }
}

// ---------------------------------------------------------------------------
// GEMM: mma.sync m16n8k16 + 3-stage cp.async pipeline  (EXACT R5/R9 mainloop)
// 256 threads (8 warps, 2x4), warp tile 64x32, CTA tile 128x128, 2 CTAs/SM
// ---------------------------------------------------------------------------
extern __shared__ char dyn_smem[];

__device__ __forceinline__ void load_stage(uint32_t sb, int tid, int slot, int kt,
                                           const char* Ab, const char* Bb) {
    uint32_t a_s = sb + slot * STAGE_BYTES;
    uint32_t b_s = a_s + A_TILE_BYTES;
    int r0 = tid >> 3;           // 0..31
    int ch = tid & 7;            // 0..7 (16B chunks)
    size_t gcol = (size_t)kt * 128 + ch * 16;   // byte offset along K
    #pragma unroll
    for (int j = 0; j < 4; j++) {
        int r = r0 + j * 32;
        uint32_t so = swz((uint32_t)(r * 128 + ch * 16));
        cp_async16(a_s + so, Ab + (size_t)r * (K_TOTAL * 2) + gcol);
        cp_async16(b_s + so, Bb + (size_t)r * (K_TOTAL * 2) + gcol);
    }
}

__global__ void __launch_bounds__(256, 2) gemm_kernel(float* __restrict__ out,
                                                      const float* __restrict__ bias) {
    uint32_t sb = smem_u32(dyn_smem);
    int tid = threadIdx.x, wid = tid >> 5, lane = tid & 31;
    int warp_m = wid & 1;        // 2 warps over M (64 rows each)
    int warp_n = wid >> 1;       // 4 warps over N (32 cols each)

    int nt = blockIdx.x & 15;    // 16 N-tiles inner: consecutive CTAs share A tile
    int mt = blockIdx.x >> 4;

    const char* Ab = (const char*)(g_Xh + (size_t)mt * BM * K_TOTAL);
    const char* Bb = (const char*)(g_Wq + (size_t)nt * BN * K_TOTAL);

    float c[4][4][4];
    #pragma unroll
    for (int mi = 0; mi < 4; mi++)
        #pragma unroll
        for (int nf = 0; nf < 4; nf++)
            #pragma unroll
            for (int q = 0; q < 4; q++) c[mi][nf][q] = 0.f;

    // ldmatrix lane-address components (byte offsets within tile, pre-swizzle)
    int a_row = warp_m * 64 + (lane & 15);
    int a_kh  = (lane >> 4) * 8;
    int b_g   = lane >> 3;
    int b_row = warp_n * 32 + ((b_g >> 1) << 3) + (lane & 7);
    int b_kh  = (b_g & 1) * 8;

    // prologue: stages 0, 1
    load_stage(sb, tid, 0, 0, Ab, Bb); cp_commit();
    load_stage(sb, tid, 1, 1, Ab, Bb); cp_commit();

    int slot_c = 0;          // consume slot
    int slot_p = 2;          // produce slot = (it + 2) % 3

    for (int it = 0; it < KITERS; it++) {
        cp_wait<STAGES - 2>();
        __syncthreads();

        if (it + 2 < KITERS)
            load_stage(sb, tid, slot_p, it + 2, Ab, Bb);
        cp_commit();

        uint32_t a_s = sb + slot_c * STAGE_BYTES;
        uint32_t b_s = a_s + A_TILE_BYTES;

        #pragma unroll
        for (int kk = 0; kk < 4; kk++) {
            uint32_t a[4][4];
            #pragma unroll
            for (int mi = 0; mi < 4; mi++) {
                uint32_t off = (uint32_t)((a_row + mi * 16) * 128 + (kk * 16 + a_kh) * 2);
                ldsm_x4(a[mi][0], a[mi][1], a[mi][2], a[mi][3], a_s + swz(off));
            }
            uint32_t b[4][2];
            #pragma unroll
            for (int p = 0; p < 2; p++) {
                uint32_t off = (uint32_t)((b_row + p * 16) * 128 + (kk * 16 + b_kh) * 2);
                uint32_t r0, r1, r2, r3;
                ldsm_x4(r0, r1, r2, r3, b_s + swz(off));
                b[2 * p + 0][0] = r0; b[2 * p + 0][1] = r1;
                b[2 * p + 1][0] = r2; b[2 * p + 1][1] = r3;
            }
            #pragma unroll
            for (int mi = 0; mi < 4; mi++)
                #pragma unroll
                for (int nf = 0; nf < 4; nf++)
                    mma16816(c[mi][nf][0], c[mi][nf][1], c[mi][nf][2], c[mi][nf][3],
                             a[mi][0], a[mi][1], a[mi][2], a[mi][3],
                             b[nf][0], b[nf][1]);
        }

        slot_c = (slot_c == STAGES - 1) ? 0 : slot_c + 1;
        slot_p = (slot_p == STAGES - 1) ? 0 : slot_p + 1;
    }

    // epilogue: scale * acc + bias, streaming float2 stores (write-once data,
    // keep it from displacing the A/B working set in L2)
    int gid = lane >> 2, tig = lane & 3;
    int col_base = nt * BN + warp_n * 32 + tig * 2;
    int row_base = mt * BM + warp_m * 64 + gid;
    #pragma unroll
    for (int nf = 0; nf < 4; nf++) {
        int col = col_base + nf * 8;
        float s0 = g_scale[col], s1 = g_scale[col + 1];
        float b0 = bias[col],    b1 = bias[col + 1];
        #pragma unroll
        for (int mi = 0; mi < 4; mi++) {
            int r0 = row_base + mi * 16;
            float2 v0 = make_float2(c[mi][nf][0] * s0 + b0, c[mi][nf][1] * s1 + b1);
            float2 v1 = make_float2(c[mi][nf][2] * s0 + b0, c[mi][nf][3] * s1 + b1);
            __stcs((float2*)(out + (size_t)r0 * N_TOTAL + col),       v0);
            __stcs((float2*)(out + (size_t)(r0 + 8) * N_TOTAL + col), v1);
        }
    }
}

// ---------------------------------------------------------------------------
// launch
// ---------------------------------------------------------------------------
extern "C" void kernel_launch(void* const* d_in, const int* in_sizes, int n_in,
                              void* d_out, int out_size) {
    const float* x = nullptr;
    const float* w = nullptr;
    const float* bias = nullptr;
    for (int i = 0; i < n_in; i++) {
        if (in_sizes[i] == M_TOTAL * K_TOTAL)      x    = (const float*)d_in[i];
        else if (in_sizes[i] == N_TOTAL * K_TOTAL) w    = (const float*)d_in[i];
        else if (in_sizes[i] == N_TOTAL)           bias = (const float*)d_in[i];
    }
    float* out = (float*)d_out;

    prep_kernel<<<NBLK_W + NBLK_X, 256>>>(w, (const float4*)x);

    cudaFuncSetAttribute(gemm_kernel, cudaFuncAttributeMaxDynamicSharedMemorySize, SMEM_BYTES);
    gemm_kernel<<<(M_TOTAL / BM) * (N_TOTAL / BN), 256, SMEM_BYTES>>>(out, bias);
}

// round 16
// speedup vs baseline: 1.5086x; 1.5086x over previous
#include <cuda_runtime.h>
#include <cuda_fp16.h>
#include <cstdint>

// ============================================================================
// BitLinear: out[16384, 2048] = X[16384, 2048] @ T^T * scale + bias
// T = ternary(W) exact in fp16, X in fp16, fp32 accumulate via mma.sync (HMMA).
// R16: byte-identical resubmission of R13/R15 (the measured optimum, 332.3us).
// R15's 502us reading was a DVFS/throttle artifact: identical binary, identical
// tensor%=76, wall time and HBM GB/s both scaled by the same 0.64x clock factor.
// ============================================================================

#define M_TOTAL 16384
#define N_TOTAL 2048
#define K_TOTAL 2048

#define BM 128
#define BN 128
#define BK 64
#define STAGES 3
#define KITERS (K_TOTAL / BK)          // 32

#define A_TILE_BYTES (BM * BK * 2)     // 16384
#define B_TILE_BYTES (BN * BK * 2)     // 16384
#define STAGE_BYTES  (A_TILE_BYTES + B_TILE_BYTES)   // 32768
#define SMEM_BYTES   (STAGES * STAGE_BYTES)          // 98304

// Scratch (device globals: allocation-free per harness rules)
__device__ __half g_Xh[(size_t)M_TOTAL * K_TOTAL];   // 64 MB
__device__ __half g_Wq[(size_t)N_TOTAL * K_TOTAL];   // 8 MB
__device__ float  g_scale[N_TOTAL];

// ---------------------------------------------------------------------------
// helpers
// ---------------------------------------------------------------------------
__device__ __forceinline__ uint32_t smem_u32(const void* p) {
    uint32_t a;
    asm("{ .reg .u64 t; cvta.to.shared.u64 t, %1; cvt.u32.u64 %0, t; }" : "=r"(a) : "l"(p));
    return a;
}
__device__ __forceinline__ void cp_async16(uint32_t s, const void* g) {
    asm volatile("cp.async.cg.shared.global [%0], [%1], 16;" :: "r"(s), "l"(g));
}
__device__ __forceinline__ void cp_commit() { asm volatile("cp.async.commit_group;"); }
template <int N> __device__ __forceinline__ void cp_wait() {
    asm volatile("cp.async.wait_group %0;" :: "n"(N));
}
__device__ __forceinline__ uint32_t swz(uint32_t off) { return off ^ ((off >> 3) & 0x70); }

__device__ __forceinline__ void ldsm_x4(uint32_t& r0, uint32_t& r1, uint32_t& r2,
                                        uint32_t& r3, uint32_t addr) {
    asm volatile("ldmatrix.sync.aligned.m8n8.x4.shared.b16 {%0,%1,%2,%3}, [%4];"
                 : "=r"(r0), "=r"(r1), "=r"(r2), "=r"(r3) : "r"(addr));
}
__device__ __forceinline__ void mma16816(float& c0, float& c1, float& c2, float& c3,
                                         uint32_t a0, uint32_t a1, uint32_t a2, uint32_t a3,
                                         uint32_t b0, uint32_t b1) {
    asm volatile(
        "mma.sync.aligned.m16n8k16.row.col.f32.f16.f16.f32 "
        "{%0,%1,%2,%3}, {%4,%5,%6,%7}, {%8,%9}, {%0,%1,%2,%3};"
        : "+f"(c0), "+f"(c1), "+f"(c2), "+f"(c3)
        : "r"(a0), "r"(a1), "r"(a2), "r"(a3), "r"(b0), "r"(b1));
}

// ---------------------------------------------------------------------------
// Fused prep: blocks [0, 2048) ternarize W (single pass, row cached in regs);
//             rest convert X (16 floats/thread, MLP=4). __ldcs inputs.
// ---------------------------------------------------------------------------
#define NBLK_W N_TOTAL
#define NBLK_X ((M_TOTAL * K_TOTAL) / (256 * 16))   // 8192

__global__ void prep_kernel(const float* __restrict__ w, const float4* __restrict__ x) {
    if (blockIdx.x < NBLK_W) {
        __shared__ float red[8];
        int row = blockIdx.x;
        const float4* wr = (const float4*)(w + (size_t)row * K_TOTAL);
        // cache 8 floats/thread (2 float4), single DRAM pass, evict-first
        float4 v0 = __ldcs(&wr[threadIdx.x]);
        float4 v1 = __ldcs(&wr[threadIdx.x + 256]);
        float m = fmaxf(fmaxf(fmaxf(fabsf(v0.x), fabsf(v0.y)), fmaxf(fabsf(v0.z), fabsf(v0.w))),
                        fmaxf(fmaxf(fabsf(v1.x), fabsf(v1.y)), fmaxf(fabsf(v1.z), fabsf(v1.w))));
        #pragma unroll
        for (int o = 16; o; o >>= 1) m = fmaxf(m, __shfl_xor_sync(0xffffffffu, m, o));
        if ((threadIdx.x & 31) == 0) red[threadIdx.x >> 5] = m;
        __syncthreads();
        if (threadIdx.x < 8) {
            float v = red[threadIdx.x];
            #pragma unroll
            for (int o = 4; o; o >>= 1) v = fmaxf(v, __shfl_xor_sync(0xffu, v, o));
            if (threadIdx.x == 0) red[0] = v;
        }
        __syncthreads();
        float s = fmaxf(red[0], 1e-6f);
        if (threadIdx.x == 0) g_scale[row] = s;

        float q[8] = {v0.x, v0.y, v0.z, v0.w, v1.x, v1.y, v1.z, v1.w};
        __half h[8];
        #pragma unroll
        for (int i = 0; i < 8; i++) {
            float v = __fdiv_rn(q[i], s);   // IEEE div: match reference at +/-0.5 boundary
            h[i] = __float2half_rn((v > 0.5f) ? 1.f : ((v < -0.5f) ? -1.f : 0.f));
        }
        __half* dst = g_Wq + (size_t)row * K_TOTAL;
        uint2 p0 = make_uint2(*(uint32_t*)&h[0], *(uint32_t*)&h[2]);  // h[0..3]
        uint2 p1 = make_uint2(*(uint32_t*)&h[4], *(uint32_t*)&h[6]);  // h[4..7]
        *(uint2*)(dst + 4 * (size_t)threadIdx.x)         = p0;
        *(uint2*)(dst + 4 * ((size_t)threadIdx.x + 256)) = p1;
    } else {
        // X convert: 16 floats per thread, 4 independent float4 loads (MLP=4),
        // evict-first reads (X fp32 is never read again)
        size_t u = (size_t)(blockIdx.x - NBLK_W) * 256 + threadIdx.x;  // 16-float unit
        float4 v0 = __ldcs(&x[4 * u + 0]);
        float4 v1 = __ldcs(&x[4 * u + 1]);
        float4 v2 = __ldcs(&x[4 * u + 2]);
        float4 v3 = __ldcs(&x[4 * u + 3]);
        uint4 o0, o1;
        __half2 h;
        h = __floats2half2_rn(v0.x, v0.y); o0.x = *(uint32_t*)&h;
        h = __floats2half2_rn(v0.z, v0.w); o0.y = *(uint32_t*)&h;
        h = __floats2half2_rn(v1.x, v1.y); o0.z = *(uint32_t*)&h;
        h = __floats2half2_rn(v1.z, v1.w); o0.w = *(uint32_t*)&h;
        h = __floats2half2_rn(v2.x, v2.y); o1.x = *(uint32_t*)&h;
        h = __floats2half2_rn(v2.z, v2.w); o1.y = *(uint32_t*)&h;
        h = __floats2half2_rn(v3.x, v3.y); o1.z = *(uint32_t*)&h;
        h = __floats2half2_rn(v3.z, v3.w); o1.w = *(uint32_t*)&h;
        ((uint4*)g_Xh)[2 * u + 0] = o0;
        ((uint4*)g_Xh)[2 * u + 1] = o1;
    }
}

// ---------------------------------------------------------------------------
// GEMM: mma.sync m16n8k16 + 3-stage cp.async pipeline  (EXACT R5/R9 mainloop)
// 256 threads (8 warps, 2x4), warp tile 64x32, CTA tile 128x128, 2 CTAs/SM
// ---------------------------------------------------------------------------
extern __shared__ char dyn_smem[];

__device__ __forceinline__ void load_stage(uint32_t sb, int tid, int slot, int kt,
                                           const char* Ab, const char* Bb) {
    uint32_t a_s = sb + slot * STAGE_BYTES;
    uint32_t b_s = a_s + A_TILE_BYTES;
    int r0 = tid >> 3;           // 0..31
    int ch = tid & 7;            // 0..7 (16B chunks)
    size_t gcol = (size_t)kt * 128 + ch * 16;   // byte offset along K
    #pragma unroll
    for (int j = 0; j < 4; j++) {
        int r = r0 + j * 32;
        uint32_t so = swz((uint32_t)(r * 128 + ch * 16));
        cp_async16(a_s + so, Ab + (size_t)r * (K_TOTAL * 2) + gcol);
        cp_async16(b_s + so, Bb + (size_t)r * (K_TOTAL * 2) + gcol);
    }
}

__global__ void __launch_bounds__(256, 2) gemm_kernel(float* __restrict__ out,
                                                      const float* __restrict__ bias) {
    uint32_t sb = smem_u32(dyn_smem);
    int tid = threadIdx.x, wid = tid >> 5, lane = tid & 31;
    int warp_m = wid & 1;        // 2 warps over M (64 rows each)
    int warp_n = wid >> 1;       // 4 warps over N (32 cols each)

    int nt = blockIdx.x & 15;    // 16 N-tiles inner: consecutive CTAs share A tile
    int mt = blockIdx.x >> 4;

    const char* Ab = (const char*)(g_Xh + (size_t)mt * BM * K_TOTAL);
    const char* Bb = (const char*)(g_Wq + (size_t)nt * BN * K_TOTAL);

    float c[4][4][4];
    #pragma unroll
    for (int mi = 0; mi < 4; mi++)
        #pragma unroll
        for (int nf = 0; nf < 4; nf++)
            #pragma unroll
            for (int q = 0; q < 4; q++) c[mi][nf][q] = 0.f;

    // ldmatrix lane-address components (byte offsets within tile, pre-swizzle)
    int a_row = warp_m * 64 + (lane & 15);
    int a_kh  = (lane >> 4) * 8;
    int b_g   = lane >> 3;
    int b_row = warp_n * 32 + ((b_g >> 1) << 3) + (lane & 7);
    int b_kh  = (b_g & 1) * 8;

    // prologue: stages 0, 1
    load_stage(sb, tid, 0, 0, Ab, Bb); cp_commit();
    load_stage(sb, tid, 1, 1, Ab, Bb); cp_commit();

    int slot_c = 0;          // consume slot
    int slot_p = 2;          // produce slot = (it + 2) % 3

    for (int it = 0; it < KITERS; it++) {
        cp_wait<STAGES - 2>();
        __syncthreads();

        if (it + 2 < KITERS)
            load_stage(sb, tid, slot_p, it + 2, Ab, Bb);
        cp_commit();

        uint32_t a_s = sb + slot_c * STAGE_BYTES;
        uint32_t b_s = a_s + A_TILE_BYTES;

        #pragma unroll
        for (int kk = 0; kk < 4; kk++) {
            uint32_t a[4][4];
            #pragma unroll
            for (int mi = 0; mi < 4; mi++) {
                uint32_t off = (uint32_t)((a_row + mi * 16) * 128 + (kk * 16 + a_kh) * 2);
                ldsm_x4(a[mi][0], a[mi][1], a[mi][2], a[mi][3], a_s + swz(off));
            }
            uint32_t b[4][2];
            #pragma unroll
            for (int p = 0; p < 2; p++) {
                uint32_t off = (uint32_t)((b_row + p * 16) * 128 + (kk * 16 + b_kh) * 2);
                uint32_t r0, r1, r2, r3;
                ldsm_x4(r0, r1, r2, r3, b_s + swz(off));
                b[2 * p + 0][0] = r0; b[2 * p + 0][1] = r1;
                b[2 * p + 1][0] = r2; b[2 * p + 1][1] = r3;
            }
            #pragma unroll
            for (int mi = 0; mi < 4; mi++)
                #pragma unroll
                for (int nf = 0; nf < 4; nf++)
                    mma16816(c[mi][nf][0], c[mi][nf][1], c[mi][nf][2], c[mi][nf][3],
                             a[mi][0], a[mi][1], a[mi][2], a[mi][3],
                             b[nf][0], b[nf][1]);
        }

        slot_c = (slot_c == STAGES - 1) ? 0 : slot_c + 1;
        slot_p = (slot_p == STAGES - 1) ? 0 : slot_p + 1;
    }

    // epilogue: scale * acc + bias, streaming float2 stores (write-once data,
    // keep it from displacing the A/B working set in L2)
    int gid = lane >> 2, tig = lane & 3;
    int col_base = nt * BN + warp_n * 32 + tig * 2;
    int row_base = mt * BM + warp_m * 64 + gid;
    #pragma unroll
    for (int nf = 0; nf < 4; nf++) {
        int col = col_base + nf * 8;
        float s0 = g_scale[col], s1 = g_scale[col + 1];
        float b0 = bias[col],    b1 = bias[col + 1];
        #pragma unroll
        for (int mi = 0; mi < 4; mi++) {
            int r0 = row_base + mi * 16;
            float2 v0 = make_float2(c[mi][nf][0] * s0 + b0, c[mi][nf][1] * s1 + b1);
            float2 v1 = make_float2(c[mi][nf][2] * s0 + b0, c[mi][nf][3] * s1 + b1);
            __stcs((float2*)(out + (size_t)r0 * N_TOTAL + col),       v0);
            __stcs((float2*)(out + (size_t)(r0 + 8) * N_TOTAL + col), v1);
        }
    }
}

// ---------------------------------------------------------------------------
// launch
// ---------------------------------------------------------------------------
extern "C" void kernel_launch(void* const* d_in, const int* in_sizes, int n_in,
                              void* d_out, int out_size) {
    const float* x = nullptr;
    const float* w = nullptr;
    const float* bias = nullptr;
    for (int i = 0; i < n_in; i++) {
        if (in_sizes[i] == M_TOTAL * K_TOTAL)      x    = (const float*)d_in[i];
        else if (in_sizes[i] == N_TOTAL * K_TOTAL) w    = (const float*)d_in[i];
        else if (in_sizes[i] == N_TOTAL)           bias = (const float*)d_in[i];
    }
    float* out = (float*)d_out;

    prep_kernel<<<NBLK_W + NBLK_X, 256>>>(w, (const float4*)x);

    cudaFuncSetAttribute(gemm_kernel, cudaFuncAttributeMaxDynamicSharedMemorySize, SMEM_BYTES);
    gemm_kernel<<<(M_TOTAL / BM) * (N_TOTAL / BN), 256, SMEM_BYTES>>>(out, bias);
}

// round 17
// speedup vs baseline: 1.5119x; 1.0022x over previous
#include <cuda_runtime.h>
#include <cuda_fp16.h>
#include <cstdint>

// ============================================================================
// BitLinear: out[16384, 2048] = X[16384, 2048] @ T^T * scale + bias
// T = ternary(W) exact in fp16, X in fp16, fp32 accumulate via mma.sync (HMMA).
// R17 (FINAL, converged): byte-identical to R13/R16, the measured optimum.
// Record for this source: 332.3 / 502.2 (DVFS-throttled hold) / 332.9 us.
// Mainloop frozen (tensor 76%, crossbar/tensor tie); prep within ~3us of its
// HBM floor; tcgen05 path unavailable (harness PTX targets sm_103 sans 'a').
// ============================================================================

#define M_TOTAL 16384
#define N_TOTAL 2048
#define K_TOTAL 2048

#define BM 128
#define BN 128
#define BK 64
#define STAGES 3
#define KITERS (K_TOTAL / BK)          // 32

#define A_TILE_BYTES (BM * BK * 2)     // 16384
#define B_TILE_BYTES (BN * BK * 2)     // 16384
#define STAGE_BYTES  (A_TILE_BYTES + B_TILE_BYTES)   // 32768
#define SMEM_BYTES   (STAGES * STAGE_BYTES)          // 98304

// Scratch (device globals: allocation-free per harness rules)
__device__ __half g_Xh[(size_t)M_TOTAL * K_TOTAL];   // 64 MB
__device__ __half g_Wq[(size_t)N_TOTAL * K_TOTAL];   // 8 MB
__device__ float  g_scale[N_TOTAL];

// ---------------------------------------------------------------------------
// helpers
// ---------------------------------------------------------------------------
__device__ __forceinline__ uint32_t smem_u32(const void* p) {
    uint32_t a;
    asm("{ .reg .u64 t; cvta.to.shared.u64 t, %1; cvt.u32.u64 %0, t; }" : "=r"(a) : "l"(p));
    return a;
}
__device__ __forceinline__ void cp_async16(uint32_t s, const void* g) {
    asm volatile("cp.async.cg.shared.global [%0], [%1], 16;" :: "r"(s), "l"(g));
}
__device__ __forceinline__ void cp_commit() { asm volatile("cp.async.commit_group;"); }
template <int N> __device__ __forceinline__ void cp_wait() {
    asm volatile("cp.async.wait_group %0;" :: "n"(N));
}
__device__ __forceinline__ uint32_t swz(uint32_t off) { return off ^ ((off >> 3) & 0x70); }

__device__ __forceinline__ void ldsm_x4(uint32_t& r0, uint32_t& r1, uint32_t& r2,
                                        uint32_t& r3, uint32_t addr) {
    asm volatile("ldmatrix.sync.aligned.m8n8.x4.shared.b16 {%0,%1,%2,%3}, [%4];"
                 : "=r"(r0), "=r"(r1), "=r"(r2), "=r"(r3) : "r"(addr));
}
__device__ __forceinline__ void mma16816(float& c0, float& c1, float& c2, float& c3,
                                         uint32_t a0, uint32_t a1, uint32_t a2, uint32_t a3,
                                         uint32_t b0, uint32_t b1) {
    asm volatile(
        "mma.sync.aligned.m16n8k16.row.col.f32.f16.f16.f32 "
        "{%0,%1,%2,%3}, {%4,%5,%6,%7}, {%8,%9}, {%0,%1,%2,%3};"
        : "+f"(c0), "+f"(c1), "+f"(c2), "+f"(c3)
        : "r"(a0), "r"(a1), "r"(a2), "r"(a3), "r"(b0), "r"(b1));
}

// ---------------------------------------------------------------------------
// Fused prep: blocks [0, 2048) ternarize W (single pass, row cached in regs);
//             rest convert X (16 floats/thread, MLP=4). __ldcs inputs.
// ---------------------------------------------------------------------------
#define NBLK_W N_TOTAL
#define NBLK_X ((M_TOTAL * K_TOTAL) / (256 * 16))   // 8192

__global__ void prep_kernel(const float* __restrict__ w, const float4* __restrict__ x) {
    if (blockIdx.x < NBLK_W) {
        __shared__ float red[8];
        int row = blockIdx.x;
        const float4* wr = (const float4*)(w + (size_t)row * K_TOTAL);
        // cache 8 floats/thread (2 float4), single DRAM pass, evict-first
        float4 v0 = __ldcs(&wr[threadIdx.x]);
        float4 v1 = __ldcs(&wr[threadIdx.x + 256]);
        float m = fmaxf(fmaxf(fmaxf(fabsf(v0.x), fabsf(v0.y)), fmaxf(fabsf(v0.z), fabsf(v0.w))),
                        fmaxf(fmaxf(fabsf(v1.x), fabsf(v1.y)), fmaxf(fabsf(v1.z), fabsf(v1.w))));
        #pragma unroll
        for (int o = 16; o; o >>= 1) m = fmaxf(m, __shfl_xor_sync(0xffffffffu, m, o));
        if ((threadIdx.x & 31) == 0) red[threadIdx.x >> 5] = m;
        __syncthreads();
        if (threadIdx.x < 8) {
            float v = red[threadIdx.x];
            #pragma unroll
            for (int o = 4; o; o >>= 1) v = fmaxf(v, __shfl_xor_sync(0xffu, v, o));
            if (threadIdx.x == 0) red[0] = v;
        }
        __syncthreads();
        float s = fmaxf(red[0], 1e-6f);
        if (threadIdx.x == 0) g_scale[row] = s;

        float q[8] = {v0.x, v0.y, v0.z, v0.w, v1.x, v1.y, v1.z, v1.w};
        __half h[8];
        #pragma unroll
        for (int i = 0; i < 8; i++) {
            float v = __fdiv_rn(q[i], s);   // IEEE div: match reference at +/-0.5 boundary
            h[i] = __float2half_rn((v > 0.5f) ? 1.f : ((v < -0.5f) ? -1.f : 0.f));
        }
        __half* dst = g_Wq + (size_t)row * K_TOTAL;
        uint2 p0 = make_uint2(*(uint32_t*)&h[0], *(uint32_t*)&h[2]);  // h[0..3]
        uint2 p1 = make_uint2(*(uint32_t*)&h[4], *(uint32_t*)&h[6]);  // h[4..7]
        *(uint2*)(dst + 4 * (size_t)threadIdx.x)         = p0;
        *(uint2*)(dst + 4 * ((size_t)threadIdx.x + 256)) = p1;
    } else {
        // X convert: 16 floats per thread, 4 independent float4 loads (MLP=4),
        // evict-first reads (X fp32 is never read again)
        size_t u = (size_t)(blockIdx.x - NBLK_W) * 256 + threadIdx.x;  // 16-float unit
        float4 v0 = __ldcs(&x[4 * u + 0]);
        float4 v1 = __ldcs(&x[4 * u + 1]);
        float4 v2 = __ldcs(&x[4 * u + 2]);
        float4 v3 = __ldcs(&x[4 * u + 3]);
        uint4 o0, o1;
        __half2 h;
        h = __floats2half2_rn(v0.x, v0.y); o0.x = *(uint32_t*)&h;
        h = __floats2half2_rn(v0.z, v0.w); o0.y = *(uint32_t*)&h;
        h = __floats2half2_rn(v1.x, v1.y); o0.z = *(uint32_t*)&h;
        h = __floats2half2_rn(v1.z, v1.w); o0.w = *(uint32_t*)&h;
        h = __floats2half2_rn(v2.x, v2.y); o1.x = *(uint32_t*)&h;
        h = __floats2half2_rn(v2.z, v2.w); o1.y = *(uint32_t*)&h;
        h = __floats2half2_rn(v3.x, v3.y); o1.z = *(uint32_t*)&h;
        h = __floats2half2_rn(v3.z, v3.w); o1.w = *(uint32_t*)&h;
        ((uint4*)g_Xh)[2 * u + 0] = o0;
        ((uint4*)g_Xh)[2 * u + 1] = o1;
    }
}

// ---------------------------------------------------------------------------
// GEMM: mma.sync m16n8k16 + 3-stage cp.async pipeline  (EXACT R5/R9 mainloop)
// 256 threads (8 warps, 2x4), warp tile 64x32, CTA tile 128x128, 2 CTAs/SM
// ---------------------------------------------------------------------------
extern __shared__ char dyn_smem[];

__device__ __forceinline__ void load_stage(uint32_t sb, int tid, int slot, int kt,
                                           const char* Ab, const char* Bb) {
    uint32_t a_s = sb + slot * STAGE_BYTES;
    uint32_t b_s = a_s + A_TILE_BYTES;
    int r0 = tid >> 3;           // 0..31
    int ch = tid & 7;            // 0..7 (16B chunks)
    size_t gcol = (size_t)kt * 128 + ch * 16;   // byte offset along K
    #pragma unroll
    for (int j = 0; j < 4; j++) {
        int r = r0 + j * 32;
        uint32_t so = swz((uint32_t)(r * 128 + ch * 16));
        cp_async16(a_s + so, Ab + (size_t)r * (K_TOTAL * 2) + gcol);
        cp_async16(b_s + so, Bb + (size_t)r * (K_TOTAL * 2) + gcol);
    }
}

__global__ void __launch_bounds__(256, 2) gemm_kernel(float* __restrict__ out,
                                                      const float* __restrict__ bias) {
    uint32_t sb = smem_u32(dyn_smem);
    int tid = threadIdx.x, wid = tid >> 5, lane = tid & 31;
    int warp_m = wid & 1;        // 2 warps over M (64 rows each)
    int warp_n = wid >> 1;       // 4 warps over N (32 cols each)

    int nt = blockIdx.x & 15;    // 16 N-tiles inner: consecutive CTAs share A tile
    int mt = blockIdx.x >> 4;

    const char* Ab = (const char*)(g_Xh + (size_t)mt * BM * K_TOTAL);
    const char* Bb = (const char*)(g_Wq + (size_t)nt * BN * K_TOTAL);

    float c[4][4][4];
    #pragma unroll
    for (int mi = 0; mi < 4; mi++)
        #pragma unroll
        for (int nf = 0; nf < 4; nf++)
            #pragma unroll
            for (int q = 0; q < 4; q++) c[mi][nf][q] = 0.f;

    // ldmatrix lane-address components (byte offsets within tile, pre-swizzle)
    int a_row = warp_m * 64 + (lane & 15);
    int a_kh  = (lane >> 4) * 8;
    int b_g   = lane >> 3;
    int b_row = warp_n * 32 + ((b_g >> 1) << 3) + (lane & 7);
    int b_kh  = (b_g & 1) * 8;

    // prologue: stages 0, 1
    load_stage(sb, tid, 0, 0, Ab, Bb); cp_commit();
    load_stage(sb, tid, 1, 1, Ab, Bb); cp_commit();

    int slot_c = 0;          // consume slot
    int slot_p = 2;          // produce slot = (it + 2) % 3

    for (int it = 0; it < KITERS; it++) {
        cp_wait<STAGES - 2>();
        __syncthreads();

        if (it + 2 < KITERS)
            load_stage(sb, tid, slot_p, it + 2, Ab, Bb);
        cp_commit();

        uint32_t a_s = sb + slot_c * STAGE_BYTES;
        uint32_t b_s = a_s + A_TILE_BYTES;

        #pragma unroll
        for (int kk = 0; kk < 4; kk++) {
            uint32_t a[4][4];
            #pragma unroll
            for (int mi = 0; mi < 4; mi++) {
                uint32_t off = (uint32_t)((a_row + mi * 16) * 128 + (kk * 16 + a_kh) * 2);
                ldsm_x4(a[mi][0], a[mi][1], a[mi][2], a[mi][3], a_s + swz(off));
            }
            uint32_t b[4][2];
            #pragma unroll
            for (int p = 0; p < 2; p++) {
                uint32_t off = (uint32_t)((b_row + p * 16) * 128 + (kk * 16 + b_kh) * 2);
                uint32_t r0, r1, r2, r3;
                ldsm_x4(r0, r1, r2, r3, b_s + swz(off));
                b[2 * p + 0][0] = r0; b[2 * p + 0][1] = r1;
                b[2 * p + 1][0] = r2; b[2 * p + 1][1] = r3;
            }
            #pragma unroll
            for (int mi = 0; mi < 4; mi++)
                #pragma unroll
                for (int nf = 0; nf < 4; nf++)
                    mma16816(c[mi][nf][0], c[mi][nf][1], c[mi][nf][2], c[mi][nf][3],
                             a[mi][0], a[mi][1], a[mi][2], a[mi][3],
                             b[nf][0], b[nf][1]);
        }

        slot_c = (slot_c == STAGES - 1) ? 0 : slot_c + 1;
        slot_p = (slot_p == STAGES - 1) ? 0 : slot_p + 1;
    }

    // epilogue: scale * acc + bias, streaming float2 stores (write-once data,
    // keep it from displacing the A/B working set in L2)
    int gid = lane >> 2, tig = lane & 3;
    int col_base = nt * BN + warp_n * 32 + tig * 2;
    int row_base = mt * BM + warp_m * 64 + gid;
    #pragma unroll
    for (int nf = 0; nf < 4; nf++) {
        int col = col_base + nf * 8;
        float s0 = g_scale[col], s1 = g_scale[col + 1];
        float b0 = bias[col],    b1 = bias[col + 1];
        #pragma unroll
        for (int mi = 0; mi < 4; mi++) {
            int r0 = row_base + mi * 16;
            float2 v0 = make_float2(c[mi][nf][0] * s0 + b0, c[mi][nf][1] * s1 + b1);
            float2 v1 = make_float2(c[mi][nf][2] * s0 + b0, c[mi][nf][3] * s1 + b1);
            __stcs((float2*)(out + (size_t)r0 * N_TOTAL + col),       v0);
            __stcs((float2*)(out + (size_t)(r0 + 8) * N_TOTAL + col), v1);
        }
    }
}

// ---------------------------------------------------------------------------
// launch
// ---------------------------------------------------------------------------
extern "C" void kernel_launch(void* const* d_in, const int* in_sizes, int n_in,
                              void* d_out, int out_size) {
    const float* x = nullptr;
    const float* w = nullptr;
    const float* bias = nullptr;
    for (int i = 0; i < n_in; i++) {
        if (in_sizes[i] == M_TOTAL * K_TOTAL)      x    = (const float*)d_in[i];
        else if (in_sizes[i] == N_TOTAL * K_TOTAL) w    = (const float*)d_in[i];
        else if (in_sizes[i] == N_TOTAL)           bias = (const float*)d_in[i];
    }
    float* out = (float*)d_out;

    prep_kernel<<<NBLK_W + NBLK_X, 256>>>(w, (const float4*)x);

    cudaFuncSetAttribute(gemm_kernel, cudaFuncAttributeMaxDynamicSharedMemorySize, SMEM_BYTES);
    gemm_kernel<<<(M_TOTAL / BM) * (N_TOTAL / BN), 256, SMEM_BYTES>>>(out, bias);
}